// round 2
// baseline (speedup 1.0000x reference)
#include <cuda_runtime.h>
#include <stdint.h>

#define NB   296          // 2 CTAs per SM on 148 SMs
#define TPB  512
#define NW   (TPB / 32)
#define KTOP 16
#define NC   (NB * KTOP)  // 4736 candidates

__device__ unsigned long long g_cand[NC];

static __device__ __forceinline__ unsigned long long make_key(float d2, int idx) {
    // d2 >= 0 -> float bits monotone as unsigned. Larger key = larger d2;
    // ties -> smaller index (via ~idx), matching jax.lax.top_k ordering.
    return (((unsigned long long)__float_as_uint(d2)) << 32) | (unsigned)(~(unsigned)idx);
}

// Warp-cooperative insert of candidate kk (per-lane) into the running top-16
// held by lanes 0..15 (mykey), with warp-uniform threshold (min of the 16).
static __device__ __forceinline__ void warp_insert(unsigned long long kk,
                                                   unsigned long long& mykey,
                                                   unsigned long long& thresh,
                                                   int lane) {
    const unsigned FULL = 0xFFFFFFFFu;
    unsigned ballot = __ballot_sync(FULL, kk > thresh);
    while (ballot) {
        int src = __ffs(ballot) - 1;
        ballot &= ballot - 1;
        unsigned long long ck = __shfl_sync(FULL, kk, src);
        if (ck > thresh) {                    // warp-uniform recheck (thresh rises)
            unsigned long long mv = (lane < 16) ? mykey : 0xFFFFFFFFFFFFFFFFULL;
            int ml = lane;
            #pragma unroll
            for (int off = 8; off; off >>= 1) {
                unsigned long long ov = __shfl_down_sync(FULL, mv, off);
                int ol = __shfl_down_sync(FULL, ml, off);
                if (ov < mv) { mv = ov; ml = ol; }
            }
            ml = __shfl_sync(FULL, ml, 0);
            if (lane == ml) mykey = ck;
            unsigned long long t = (lane < 16) ? mykey : 0xFFFFFFFFFFFFFFFFULL;
            #pragma unroll
            for (int off = 8; off; off >>= 1) {
                unsigned long long ot = __shfl_down_sync(FULL, t, off);
                t = (ot < t) ? ot : t;
            }
            thresh = __shfl_sync(FULL, t, 0);
        }
    }
}

__global__ void __launch_bounds__(TPB) locse_scan(const float* __restrict__ P,
                                                  const int* __restrict__ iptr,
                                                  int n) {
    int lane = threadIdx.x & 31;
    int wid  = threadIdx.x >> 5;
    const int T = NB * TPB;
    const int NP = n >> 1;                 // point pairs (n is even: 8M)
    const float4* __restrict__ P4 = (const float4*)P;

    int qi = *iptr;
    float pix = __ldg(P + (size_t)qi * 6 + 0);
    float piy = __ldg(P + (size_t)qi * 6 + 1);
    float piz = __ldg(P + (size_t)qi * 6 + 2);

    unsigned long long mykey  = 0ULL;
    unsigned long long thresh = 0ULL;

    // warp-uniform outer loop over pair-index base; unroll x2 for MLP=6 LDG.128
    for (int base = blockIdx.x * TPB + wid * 32; base < NP; base += 2 * T) {
        int q0 = base + lane;
        int q1 = q0 + T;
        bool v0 = q0 < NP, v1 = q1 < NP;

        float4 a0, b0, c0, a1, b1, c1;
        if (v0) {                          // pair q0 -> points 2q0, 2q0+1
            a0 = P4[(size_t)3 * q0];
            b0 = P4[(size_t)3 * q0 + 1];
            c0 = P4[(size_t)3 * q0 + 2];
        }
        if (v1) {
            a1 = P4[(size_t)3 * q1];
            b1 = P4[(size_t)3 * q1 + 1];
            c1 = P4[(size_t)3 * q1 + 2];
        }

        unsigned long long k00 = 0ULL, k01 = 0ULL, k10 = 0ULL, k11 = 0ULL;
        if (v0) {
            float dx = a0.x - pix, dy = a0.y - piy, dz = a0.z - piz;
            k00 = make_key(dx * dx + dy * dy + dz * dz, 2 * q0);
            dx = b0.z - pix; dy = b0.w - piy; dz = c0.x - piz;
            k01 = make_key(dx * dx + dy * dy + dz * dz, 2 * q0 + 1);
        }
        if (v1) {
            float dx = a1.x - pix, dy = a1.y - piy, dz = a1.z - piz;
            k10 = make_key(dx * dx + dy * dy + dz * dz, 2 * q1);
            dx = b1.z - pix; dy = b1.w - piy; dz = c1.x - piz;
            k11 = make_key(dx * dx + dy * dy + dz * dz, 2 * q1 + 1);
        }

        warp_insert(k00, mykey, thresh, lane);
        warp_insert(k01, mykey, thresh, lane);
        warp_insert(k10, mykey, thresh, lane);
        warp_insert(k11, mykey, thresh, lane);
    }

    // block merge: NW*16 = 256 candidates -> top 16 -> global
    __shared__ unsigned long long s_c[NW * KTOP];
    if (lane < KTOP) s_c[wid * KTOP + lane] = mykey;
    __syncthreads();

    if (wid == 0) {
        const unsigned FULL = 0xFFFFFFFFu;
        unsigned long long e[NW * KTOP / 32];
        #pragma unroll
        for (int j = 0; j < NW * KTOP / 32; j++) e[j] = s_c[lane + 32 * j];
        for (int r = 0; r < KTOP; r++) {
            unsigned long long lm = 0ULL; int ls = 0;
            #pragma unroll
            for (int j = 0; j < NW * KTOP / 32; j++)
                if (e[j] > lm) { lm = e[j]; ls = j; }
            unsigned long long wm = lm;
            #pragma unroll
            for (int off = 16; off; off >>= 1) {
                unsigned long long o = __shfl_xor_sync(FULL, wm, off);
                wm = (o > wm) ? o : wm;
            }
            if (lm == wm && lm != 0ULL) e[ls] = 0ULL;   // keys unique -> one clear
            if (lane == 0) g_cand[blockIdx.x * KTOP + r] = wm;
        }
    }
}

// Single-warp final selection over the 4736 candidates + epilogue.
__global__ void __launch_bounds__(32) locse_final(const float* __restrict__ P,
                                                  const float* __restrict__ W,
                                                  const float* __restrict__ bb,
                                                  const int* __restrict__ iptr,
                                                  float* __restrict__ out) {
    const unsigned FULL = 0xFFFFFFFFu;
    int lane = threadIdx.x;

    unsigned long long mykey  = 0ULL;
    unsigned long long thresh = 0ULL;

    // NC = 4736 = 148 * 32 : exact, no tail. Unroll x4 for MLP.
    #pragma unroll 1
    for (int j = lane; j < NC; j += 128) {
        unsigned long long k0 = g_cand[j];
        unsigned long long k1 = g_cand[j + 32];
        unsigned long long k2 = g_cand[j + 64];
        unsigned long long k3 = g_cand[j + 96];
        warp_insert(k0, mykey, thresh, lane);
        warp_insert(k1, mykey, thresh, lane);
        warp_insert(k2, mykey, thresh, lane);
        warp_insert(k3, mykey, thresh, lane);
    }

    // rank-sort the 16 winners (keys unique): rank = #{keys greater}
    unsigned long long key = (lane < 16) ? mykey : 0ULL;
    int rank = 0;
    #pragma unroll
    for (int j = 0; j < KTOP; j++) {
        unsigned long long o = __shfl_sync(FULL, key, j);
        if (lane < 16 && o > key) rank++;
    }
    __shared__ unsigned long long s_top[KTOP];
    if (lane < 16) s_top[rank] = key;
    __syncwarp();

    if (lane < KTOP) {
        unsigned long long k = s_top[lane];
        int idx = (int)(~(unsigned)(k & 0xFFFFFFFFULL));
        int qi = *iptr;
        float pix = P[(size_t)qi * 6 + 0];
        float piy = P[(size_t)qi * 6 + 1];
        float piz = P[(size_t)qi * 6 + 2];
        float nx = P[(size_t)idx * 6 + 0];
        float ny = P[(size_t)idx * 6 + 1];
        float nz = P[(size_t)idx * 6 + 2];
        float dx = pix - nx, dy = piy - ny, dz = piz - nz;
        float dist = sqrtf(dx * dx + dy * dy + dz * dz);
        float feat[10] = {pix, piy, piz, nx, ny, nz, dx, dy, dz, dist};
        out[lane * 6 + 0] = nx;
        out[lane * 6 + 1] = ny;
        out[lane * 6 + 2] = nz;
        #pragma unroll
        for (int j = 0; j < 3; j++) {
            float acc = bb[j];
            #pragma unroll
            for (int q = 0; q < 10; q++) acc += feat[q] * W[j * 10 + q];
            out[lane * 6 + 3 + j] = acc;
        }
    }
}

extern "C" void kernel_launch(void* const* d_in, const int* in_sizes, int n_in,
                              void* d_out, int out_size) {
    const float* P  = (const float*)d_in[0];
    const float* W  = (const float*)d_in[1];
    const float* b  = (const float*)d_in[2];
    const int*   ip = (const int*)d_in[3];
    float* out = (float*)d_out;
    int n = in_sizes[0] / 6;

    locse_scan<<<NB, TPB>>>(P, ip, n);
    locse_final<<<1, 32>>>(P, W, b, ip, out);
}

// round 3
// speedup vs baseline: 2.2283x; 2.2283x over previous
#include <cuda_runtime.h>
#include <stdint.h>

#define NB       296
#define TPB      512
#define NWARP    (TPB / 32)        // 16
#define KTOP     16
#define NC       (NB * KTOP)       // 4736
#define TILE_PTS (TPB * 2)         // 1024 points / tile
#define TILE_F4  (TILE_PTS * 6 / 4)// 1536 float4 = 24 KB

typedef unsigned long long u64;

__device__ u64 g_cand[NC];

static __device__ __forceinline__ u64 make_key(float d2, int idx) {
    // d2 >= 0 -> float bits monotone. Larger key = larger d2; ties -> smaller
    // index (via ~idx), matching jax.lax.top_k.
    return (((u64)__float_as_uint(d2)) << 32) | (unsigned)(~(unsigned)idx);
}

// min of mykey over lanes 0..15, returned warp-uniform (lanes>=16 feed ~0)
static __device__ __forceinline__ u64 warp_min16(u64 mykey, int lane) {
    u64 t = (lane < 16) ? mykey : 0xFFFFFFFFFFFFFFFFULL;
    #pragma unroll
    for (int off = 16; off; off >>= 1) {
        u64 o = __shfl_xor_sync(0xFFFFFFFFu, t, off);
        t = o < t ? o : t;
    }
    return t;
}

// Insert per-lane candidate kk into running top-16 (lanes 0..15 hold mykey).
static __device__ __forceinline__ void warp_insert(u64 kk, u64& mykey,
                                                   u64& thresh, int lane) {
    const unsigned FULL = 0xFFFFFFFFu;
    unsigned bal = __ballot_sync(FULL, kk > thresh);
    while (bal) {
        int src = __ffs(bal) - 1;
        bal &= bal - 1;
        u64 ck = __shfl_sync(FULL, kk, src);
        if (ck > thresh) {   // warp-uniform (thresh may have risen)
            unsigned who = __ballot_sync(FULL, (lane < 16) & (mykey == thresh));
            int ml = __ffs(who) - 1;
            if (lane == ml) mykey = ck;
            thresh = warp_min16(mykey, lane);
        }
    }
}

// Bitonic sort, descending, values live in lanes 0..15 (j<=8 keeps halves separate)
static __device__ __forceinline__ u64 sort16_desc(u64 v, int lane) {
    #pragma unroll
    for (int k = 2; k <= 16; k <<= 1) {
        #pragma unroll
        for (int j = k >> 1; j > 0; j >>= 1) {
            u64 o = __shfl_xor_sync(0xFFFFFFFFu, v, j);
            bool up = ((lane & k) == 0);
            bool lower = ((lane & j) == 0);
            v = ((lower == up) ? (v > o) : (v < o)) ? v : o;
        }
    }
    return v;
}

// Merge descending sorted A (register, lanes 0..15) with descending sorted B
// (shared, 16 keys) -> top-16 descending in lanes 0..15.
static __device__ __forceinline__ u64 merge16_desc(u64 a, const u64* Bs, int lane) {
    u64 b = Bs[15 - (lane & 15)];
    u64 c = a > b ? a : b;          // bitonic top-16
    #pragma unroll
    for (int j = 8; j > 0; j >>= 1) {
        u64 o = __shfl_xor_sync(0xFFFFFFFFu, c, j);
        c = (((lane & j) == 0) ? (c > o) : (c < o)) ? c : o;
    }
    return c;
}

__global__ void __launch_bounds__(TPB, 2) locse_scan(const float* __restrict__ P,
                                                     const int* __restrict__ iptr,
                                                     int n, int f4max, int ntiles) {
    __shared__ float4 s_tile[TILE_F4];
    const float4* __restrict__ P4 = (const float4*)P;
    int t = threadIdx.x, lane = t & 31, wid = t >> 5;

    int qi = *iptr;
    float pix = __ldg(P + (size_t)qi * 6 + 0);
    float piy = __ldg(P + (size_t)qi * 6 + 1);
    float piz = __ldg(P + (size_t)qi * 6 + 2);

    u64 mykey = 0ULL, thresh = 0ULL;

    // prologue: prefetch tile blockIdx.x
    int tile = blockIdx.x;
    int base = tile * TILE_F4;
    float4 r0 = __ldg(P4 + min(base + t,            f4max - 1));
    float4 r1 = __ldg(P4 + min(base + t + TPB,      f4max - 1));
    float4 r2 = __ldg(P4 + min(base + t + 2 * TPB,  f4max - 1));

    for (; tile < ntiles; tile += NB) {
        __syncthreads();                     // prev compute done reading shared
        s_tile[t]           = r0;
        s_tile[t + TPB]     = r1;
        s_tile[t + 2 * TPB] = r2;
        __syncthreads();

        // prefetch next tile (clamped, unconditional -> stays batched/in-flight)
        int nb = (tile + NB) * TILE_F4;
        r0 = __ldg(P4 + min(nb + t,           f4max - 1));
        r1 = __ldg(P4 + min(nb + t + TPB,     f4max - 1));
        r2 = __ldg(P4 + min(nb + t + 2 * TPB, f4max - 1));

        // compute 2 points from shared
        const float* sf = (const float*)s_tile;
        int p0 = tile * TILE_PTS + t;
        int p1 = p0 + TPB;
        float x0 = sf[6 * t + 0], y0 = sf[6 * t + 1], z0 = sf[6 * t + 2];
        int t2 = t + TPB;
        float x1 = sf[6 * t2 + 0], y1 = sf[6 * t2 + 1], z1 = sf[6 * t2 + 2];

        float dx = x0 - pix, dy = y0 - piy, dz = z0 - piz;
        u64 k0 = (p0 < n) ? make_key(dx * dx + dy * dy + dz * dz, p0) : 0ULL;
        dx = x1 - pix; dy = y1 - piy; dz = z1 - piz;
        u64 k1 = (p1 < n) ? make_key(dx * dx + dy * dy + dz * dz, p1) : 0ULL;

        warp_insert(k0, mykey, thresh, lane);
        warp_insert(k1, mykey, thresh, lane);
    }

    // per-warp sort -> shared -> tree merge 16 lists -> block top-16 (descending)
    u64 sk = sort16_desc((lane < 16) ? mykey : 0ULL, lane);
    __syncthreads();
    u64* sm = (u64*)s_tile;
    if (lane < 16) sm[wid * 16 + lane] = sk;
    __syncthreads();
    #pragma unroll
    for (int nact = 8; nact >= 1; nact >>= 1) {
        u64 c = 0ULL;
        if (wid < nact) {
            c = sm[(2 * wid) * 16 + (lane & 15)];
            c = merge16_desc(c, &sm[(2 * wid + 1) * 16], lane);
        }
        __syncthreads();
        if (wid < nact && lane < 16) sm[wid * 16 + lane] = c;
        __syncthreads();
    }
    if (t < KTOP) g_cand[blockIdx.x * KTOP + t] = sm[t];
}

__global__ void __launch_bounds__(256) locse_final(const float* __restrict__ P,
                                                   const float* __restrict__ W,
                                                   const float* __restrict__ bb,
                                                   const int* __restrict__ iptr,
                                                   float* __restrict__ out) {
    __shared__ u64 s[NC];          // 37888 B
    __shared__ u64 sm[8 * KTOP];
    int t = threadIdx.x, lane = t & 31, wid = t >> 5;

    for (int j = t; j < NC; j += 256) s[j] = g_cand[j];
    __syncthreads();

    // each warp covers 37 blocks, processed rank-major (block maxima first)
    u64 mykey = 0ULL, thresh = 0ULL;
    int b0 = 37 * wid;
    #pragma unroll 1
    for (int r = 0; r < KTOP; r++) {
        u64 ka = s[(b0 + lane) * KTOP + r];
        u64 kb = (lane < 5) ? s[(b0 + 32 + lane) * KTOP + r] : 0ULL;
        warp_insert(ka, mykey, thresh, lane);
        warp_insert(kb, mykey, thresh, lane);
    }

    u64 sk = sort16_desc((lane < 16) ? mykey : 0ULL, lane);
    if (lane < 16) sm[wid * 16 + lane] = sk;
    __syncthreads();
    #pragma unroll
    for (int nact = 4; nact >= 1; nact >>= 1) {
        u64 c = 0ULL;
        if (wid < nact) {
            c = sm[(2 * wid) * 16 + (lane & 15)];
            c = merge16_desc(c, &sm[(2 * wid + 1) * 16], lane);
        }
        __syncthreads();
        if (wid < nact && lane < 16) sm[wid * 16 + lane] = c;
        __syncthreads();
    }

    if (t < KTOP) {
        u64 k = sm[t];
        int idx = (int)(~(unsigned)(k & 0xFFFFFFFFULL));
        int qi = *iptr;
        float pix = P[(size_t)qi * 6 + 0];
        float piy = P[(size_t)qi * 6 + 1];
        float piz = P[(size_t)qi * 6 + 2];
        float nx = P[(size_t)idx * 6 + 0];
        float ny = P[(size_t)idx * 6 + 1];
        float nz = P[(size_t)idx * 6 + 2];
        float dx = pix - nx, dy = piy - ny, dz = piz - nz;
        float dist = sqrtf(dx * dx + dy * dy + dz * dz);
        float feat[10] = {pix, piy, piz, nx, ny, nz, dx, dy, dz, dist};
        out[t * 6 + 0] = nx;
        out[t * 6 + 1] = ny;
        out[t * 6 + 2] = nz;
        #pragma unroll
        for (int j = 0; j < 3; j++) {
            float acc = bb[j];
            #pragma unroll
            for (int q = 0; q < 10; q++) acc += feat[q] * W[j * 10 + q];
            out[t * 6 + 3 + j] = acc;
        }
    }
}

extern "C" void kernel_launch(void* const* d_in, const int* in_sizes, int n_in,
                              void* d_out, int out_size) {
    const float* P  = (const float*)d_in[0];
    const float* W  = (const float*)d_in[1];
    const float* b  = (const float*)d_in[2];
    const int*   ip = (const int*)d_in[3];
    float* out = (float*)d_out;
    int n = in_sizes[0] / 6;
    int f4max = in_sizes[0] / 4;                 // number of full float4s in P
    int ntiles = (n + TILE_PTS - 1) / TILE_PTS;

    locse_scan<<<NB, TPB>>>(P, ip, n, f4max, ntiles);
    locse_final<<<1, 256>>>(P, W, b, ip, out);
}